// round 11
// baseline (speedup 1.0000x reference)
#include <cuda_runtime.h>
#include <cuda_fp16.h>
#include <cstdint>
#include <cstddef>

// ---------------------------------------------------------------------------
// StyleLayer via single-pass fp16 mma.sync (fp32 accum), warp-specialized
// producer/consumer mbarrier pipeline, static smem (32.8KB), no host APIs.
//   style  = w @ (affine_w*AFF_SCALE)^T + affine_b
//   dcoef  = CONV_SCALE * rsqrt(CONV_SCALE^2 * sum_c style^2*wsq + 1e-8)
//   planes: P[b][c][s][y][px] = pad(x*style)[b,c,y,px+s]   (fp16)
//   WT[k'=t*512+c][o] = conv_w[o][c][t]                     (fp16, K-major)
//   D = W * P, epilogue: *dcoef + noise*ns + bias -> lrelu*sqrt2
// GEMM per sample: M=512, N=4096, K=4608.
// CTA 128x128, K-chunk 32, 2-stage mbarrier pipeline, 160 threads:
// 4 compute warps (2M x 2N, warp 64x64) + 1 producer warp. occ 2.
// ---------------------------------------------------------------------------

#define B_      8
#define CIN_    512
#define COUT_   512
#define SDIM_   512
#define NPIX_   4096
#define KDIM_   4608
#define AFF_SCALE   0.044194173824159216f
#define CONV_SCALE  0.014731391274719739f
#define LRELU_GAIN  1.4142135623730951f

#define PLANE_ELEMS ((size_t)B_ * CIN_ * 3 * 66 * 64)
__device__ __align__(16) static __half g_pf[PLANE_ELEMS];
__device__ __align__(16) static __half g_wfT[KDIM_ * COUT_];   // [k'][o]
__device__ static float g_style[B_ * CIN_];
__device__ static float g_wsq[COUT_ * CIN_];
__device__ static float g_dcoef[B_ * COUT_];

// ---------------- prep kernels ----------------

__global__ void prep_style(const float* __restrict__ w,
                           const float* __restrict__ affine_w,
                           const float* __restrict__ affine_b) {
    __shared__ float ws[SDIM_];
    const int b = blockIdx.x, c = threadIdx.x;
    ws[c] = w[b * SDIM_ + c];
    __syncthreads();
    const float* ar = affine_w + c * SDIM_;
    float s = 0.f;
    #pragma unroll 8
    for (int k = 0; k < SDIM_; ++k) s += ws[k] * ar[k];
    g_style[b * CIN_ + c] = s * AFF_SCALE + affine_b[c];
}

__global__ void prep_wsq(const float* __restrict__ conv_w) {
    const int idx = blockIdx.x * blockDim.x + threadIdx.x;
    if (idx >= COUT_ * CIN_) return;
    const float* p = conv_w + idx * 9;
    float s = 0.f;
    #pragma unroll
    for (int t = 0; t < 9; ++t) s += p[t] * p[t];
    g_wsq[idx] = s;
}

__global__ void prep_dcoef() {
    __shared__ float s2[CIN_];
    const int b = blockIdx.x, o = threadIdx.x;
    const float st = g_style[b * CIN_ + o];
    s2[o] = st * st;
    __syncthreads();
    const float* wr = g_wsq + o * CIN_;
    float s = 0.f;
    #pragma unroll 8
    for (int c = 0; c < CIN_; ++c) s += s2[c] * wr[c];
    g_dcoef[b * COUT_ + o] =
        CONV_SCALE * rsqrtf(CONV_SCALE * CONV_SCALE * s + 1e-8f);
}

// g_wfT[(t*512+c)*512 + o] = conv_w[o][c][t]  (coalesced writes)
__global__ void prep_wfT(const float* __restrict__ conv_w) {
    const int idx = blockIdx.x * 256 + threadIdx.x;   // k'*512 + o
    const int o = idx & 511;
    const int kp = idx >> 9;
    const int t = kp >> 9;
    const int c = kp & 511;
    g_wfT[idx] = __float2half_rn(conv_w[(size_t)o * KDIM_ + c * 9 + t]);
}

__global__ void prep_planes(const float* __restrict__ x) {
    const int idx = blockIdx.x * 256 + threadIdx.x;
    const int px = idx & 63;
    int rest = idx >> 6;
    const int y = rest % 66;
    rest /= 66;
    const int s = rest % 3;
    const int bc = rest / 3;
    const int xc = px + s - 1;
    float v = 0.f;
    if (y >= 1 && y <= 64 && xc >= 0 && xc < 64)
        v = x[((size_t)bc << 12) + ((y - 1) << 6) + xc] * g_style[bc];
    g_pf[idx] = __float2half_rn(v);
}

// ---------------- main GEMM ----------------
// grid (4 m, 32 n, 8 b), 160 threads: warps 0-3 compute, warp 4 producer.
// stage 16KB: A [32k][16u of 16B] K-major swizzled; B same geometry.
// 2 stages + 4 mbarriers (full0,full1,empty0,empty1), all static smem.

#define NC 144
#define ABYTES 8192
#define STAGE  16384

__device__ __forceinline__ void cpa16(uint32_t dst, const void* src) {
    asm volatile("cp.async.cg.shared.global [%0], [%1], 16;"
                 :: "r"(dst), "l"(src) : "memory");
}

__device__ __forceinline__ void mbar_init(uint32_t a, uint32_t cnt) {
    asm volatile("mbarrier.init.shared.b64 [%0], %1;" :: "r"(a), "r"(cnt)
                 : "memory");
}

__device__ __forceinline__ void mbar_wait(uint32_t a, uint32_t parity) {
    asm volatile(
        "{\n\t.reg .pred P;\n\t"
        "W_%=:\n\t"
        "mbarrier.try_wait.parity.acquire.cta.shared::cta.b64 P, [%0], %1;\n\t"
        "@!P bra W_%=;\n\t}"
        :: "r"(a), "r"(parity) : "memory");
}

__device__ __forceinline__ void mbar_arrive_rel(uint32_t a) {
    asm volatile("mbarrier.arrive.release.cta.shared::cta.b64 _, [%0];"
                 :: "r"(a) : "memory");
}

__device__ __forceinline__ void cpasync_arrive(uint32_t a) {
    asm volatile("cp.async.mbarrier.arrive.noinc.shared::cta.b64 [%0];"
                 :: "r"(a) : "memory");
}

__device__ __forceinline__ void ldsm4t(uint32_t* r, uint32_t a) {
    asm volatile("ldmatrix.sync.aligned.m8n8.x4.trans.shared.b16 {%0,%1,%2,%3}, [%4];"
                 : "=r"(r[0]), "=r"(r[1]), "=r"(r[2]), "=r"(r[3]) : "r"(a));
}

__device__ __forceinline__ void mma16816(float* d, const uint32_t* a,
                                         uint32_t b0, uint32_t b1) {
    asm volatile(
        "mma.sync.aligned.m16n8k16.row.col.f32.f16.f16.f32 "
        "{%0,%1,%2,%3}, {%4,%5,%6,%7}, {%8,%9}, {%0,%1,%2,%3};"
        : "+f"(d[0]), "+f"(d[1]), "+f"(d[2]), "+f"(d[3])
        : "r"(a[0]), "r"(a[1]), "r"(a[2]), "r"(a[3]), "r"(b0), "r"(b1));
}

__global__ __launch_bounds__(160, 2)
void conv_mma(const float* __restrict__ noise, const float* __restrict__ nscale,
              const float* __restrict__ bias, float* __restrict__ out) {
    __shared__ __align__(16) char smem[2 * STAGE];     // 32KB data
    __shared__ __align__(8)  unsigned long long bars[4]; // full0,full1,empty0,empty1
    const uint32_t sbase = (uint32_t)__cvta_generic_to_shared(smem);
    const uint32_t bbase = (uint32_t)__cvta_generic_to_shared(bars);
    const int tid = threadIdx.x;
    const int wid = tid >> 5;
    const int lane = tid & 31;
    const int m0 = blockIdx.x * 128;
    const int n0 = blockIdx.y * 128;   // pixel offset (= 2 image rows)
    const int py0 = blockIdx.y * 2;
    const int b = blockIdx.z;

    if (tid == 0) {
        mbar_init(bbase + 0,  32);   // full0  (producer threads)
        mbar_init(bbase + 8,  32);   // full1
        mbar_init(bbase + 16, 128);  // empty0 (consumer threads)
        mbar_init(bbase + 24, 128);  // empty1
    }
    __syncthreads();

    if (wid == 4) {
        // ================= producer warp =================
        for (int kc = 0; kc < NC; ++kc) {
            const int st = kc & 1;
            const int n = kc >> 1;
            if (kc >= 2) mbar_wait(bbase + 16 + st * 8, (n - 1) & 1);
            const int t = kc >> 4;               // 0..8
            const int c0 = (kc & 15) << 5;       // 0..480
            const int r = t / 3, s = t - 3 * r;
            const uint32_t A0 = sbase + st * STAGE;
            const uint32_t B0 = A0 + ABYTES;
            // A: 512 units of 16B
            #pragma unroll
            for (int i = 0; i < 16; ++i) {
                const int v = lane + (i << 5);
                const int k = v >> 4, u = v & 15;
                const __half* src = g_wfT + (size_t)(t * 512 + c0 + k) * COUT_
                                  + m0 + (u << 3);
                const uint32_t col = (u & ~7) | ((u & 7) ^ (k & 7));
                cpa16(A0 + (k << 8) + (col << 4), src);
            }
            // B: 512 units of 16B
            #pragma unroll
            for (int i = 0; i < 16; ++i) {
                const int v = lane + (i << 5);
                const int k = v >> 4, u = v & 15;
                const __half* src = g_pf
                    + ((((size_t)(b * 512 + c0 + k) * 3 + s) * 66)
                       + (py0 + (u >> 3) + r)) * 64 + ((u & 7) << 3);
                const uint32_t col = (u & ~7) | ((u & 7) ^ (k & 7));
                cpa16(B0 + (k << 8) + (col << 4), src);
            }
            cpasync_arrive(bbase + st * 8);
        }
        return;
    }

    // ================= consumer warps (0-3) =================
    const int wm = wid >> 1;           // 0..1  (m offset 64*wm)
    const int wn = wid & 1;            // 0..1  (n offset 64*wn)

    float acc[4][8][4];
    #pragma unroll
    for (int i = 0; i < 4; ++i)
        #pragma unroll
        for (int j = 0; j < 8; ++j)
            #pragma unroll
            for (int e = 0; e < 4; ++e) acc[i][j][e] = 0.f;

    // A (trans): m-half from lane bit3, k-half from lane bit4
    const int akrow = (lane & 7) + ((lane >> 4) & 1) * 8;
    const int auoff = (lane >> 3) & 1;
    // B (trans): k-half from lane bit3, u from lane bit4
    const int bkrow = (lane & 7) + ((lane >> 3) & 1) * 8;

    for (int kc = 0; kc < NC; ++kc) {
        const int st = kc & 1;
        const int ph = (kc >> 1) & 1;
        mbar_wait(bbase + st * 8, ph);

        const uint32_t A0 = sbase + st * STAGE;
        const uint32_t B0 = A0 + ABYTES;

        #pragma unroll
        for (int kh = 0; kh < 2; ++kh) {
            uint32_t af[4][4], bf[4][4];
            const int ka = kh * 16 + akrow;
            #pragma unroll
            for (int mf = 0; mf < 4; ++mf) {
                const int u = wm * 8 + mf * 2 + auoff;
                const uint32_t col = (u & ~7) | ((u & 7) ^ (ka & 7));
                ldsm4t(af[mf], A0 + (ka << 8) + (col << 4));
            }
            const int kb = kh * 16 + bkrow;
            #pragma unroll
            for (int nb = 0; nb < 4; ++nb) {
                const int u = wn * 8 + nb * 2 + (lane >> 4);
                const uint32_t col = (u & ~7) | ((u & 7) ^ (kb & 7));
                ldsm4t(bf[nb], B0 + (kb << 8) + (col << 4));
            }
            #pragma unroll
            for (int mf = 0; mf < 4; ++mf)
                #pragma unroll
                for (int nb = 0; nb < 4; ++nb)
                    #pragma unroll
                    for (int h = 0; h < 2; ++h)
                        mma16816(acc[mf][nb * 2 + h], af[mf],
                                 bf[nb][h * 2], bf[nb][h * 2 + 1]);
        }
        mbar_arrive_rel(bbase + 16 + st * 8);
    }

    // ---- epilogue (consumer warps only) ----
    const float ns = nscale[0];
    const int lr = lane >> 2;
    const int lc = (lane & 3) * 2;
    const int nbase = n0 + wn * 64 + lc;
    float nz[8][2];
    #pragma unroll
    for (int n8 = 0; n8 < 8; ++n8) {
        nz[n8][0] = noise[b * NPIX_ + nbase + n8 * 8] * ns;
        nz[n8][1] = noise[b * NPIX_ + nbase + n8 * 8 + 1] * ns;
    }
    #pragma unroll
    for (int mf = 0; mf < 4; ++mf) {
        const int row0 = m0 + wm * 64 + mf * 16 + lr;
        const int row1 = row0 + 8;
        const float dc0 = g_dcoef[b * COUT_ + row0], bi0 = bias[row0];
        const float dc1 = g_dcoef[b * COUT_ + row1], bi1 = bias[row1];
        #pragma unroll
        for (int n8 = 0; n8 < 8; ++n8) {
            const int n = nbase + n8 * 8;
            const float* d = acc[mf][n8];
            float v0 = d[0] * dc0 + nz[n8][0] + bi0;
            float v1 = d[1] * dc0 + nz[n8][1] + bi0;
            float v2 = d[2] * dc1 + nz[n8][0] + bi1;
            float v3 = d[3] * dc1 + nz[n8][1] + bi1;
            v0 = (v0 > 0.f) ? v0 * LRELU_GAIN : v0 * (0.2f * LRELU_GAIN);
            v1 = (v1 > 0.f) ? v1 * LRELU_GAIN : v1 * (0.2f * LRELU_GAIN);
            v2 = (v2 > 0.f) ? v2 * LRELU_GAIN : v2 * (0.2f * LRELU_GAIN);
            v3 = (v3 > 0.f) ? v3 * LRELU_GAIN : v3 * (0.2f * LRELU_GAIN);
            float* o0 = out + ((size_t)(b * COUT_ + row0)) * NPIX_ + n;
            float* o1 = out + ((size_t)(b * COUT_ + row1)) * NPIX_ + n;
            *reinterpret_cast<float2*>(o0) = make_float2(v0, v1);
            *reinterpret_cast<float2*>(o1) = make_float2(v2, v3);
        }
    }
}

// ---------------- launch ----------------

extern "C" void kernel_launch(void* const* d_in, const int* in_sizes, int n_in,
                              void* d_out, int out_size) {
    (void)in_sizes; (void)n_in; (void)out_size;
    const float* x        = (const float*)d_in[0];
    const float* w        = (const float*)d_in[1];
    const float* noise    = (const float*)d_in[2];
    const float* affine_w = (const float*)d_in[3];
    const float* affine_b = (const float*)d_in[4];
    const float* conv_w   = (const float*)d_in[5];
    const float* nscale   = (const float*)d_in[6];
    const float* bias     = (const float*)d_in[7];
    float* out = (float*)d_out;

    prep_style<<<B_, SDIM_>>>(w, affine_w, affine_b);
    prep_wsq<<<(COUT_ * CIN_) / 256, 256>>>(conv_w);
    prep_dcoef<<<B_, COUT_>>>();
    prep_wfT<<<(KDIM_ * COUT_) / 256, 256>>>(conv_w);
    prep_planes<<<(int)(PLANE_ELEMS / 256), 256>>>(x);

    conv_mma<<<dim3(4, 32, 8), 160>>>(noise, nscale, bias, out);
}